// round 5
// baseline (speedup 1.0000x reference)
#include <cuda_runtime.h>

#define N_NODES   50000
#define N_EDGES   800000
#define F_IN      16
#define F_EDGE    8
#define H         8
#define NUM_GRAPHS 512

// ---------------- scratch (no allocations allowed) ----------------
__device__ float g_y1 [N_NODES * F_EDGE * H];   // y1[n][o][j]
__device__ float g_xb1[N_NODES * H];
__device__ float g_agg1[N_NODES * H];
__device__ float g_y2 [N_NODES * F_EDGE * H];
__device__ float g_xb2[N_NODES * H];
__device__ float g_agg2[N_NODES * H];

__device__ __forceinline__ void red_add_v4(float* p, float4 v) {
    asm volatile("red.global.add.v4.f32 [%0], {%1,%2,%3,%4};"
                 :: "l"(p), "f"(v.x), "f"(v.y), "f"(v.z), "f"(v.w) : "memory");
}

// ---------------- kernel A: per-node precompute for layer 1 ----------------
__global__ void node_pre1(const float* __restrict__ x,
                          const float* __restrict__ We1,
                          const float* __restrict__ be1,
                          const float* __restrict__ root1,
                          const float* __restrict__ b1,
                          int N)
{
    __shared__ float sW[F_EDGE * F_IN * H];   // 1024
    __shared__ float sbe[F_IN * H];
    __shared__ float sroot[F_IN * H];
    __shared__ float sb[H];

    for (int t = threadIdx.x; t < F_EDGE * F_IN * H; t += blockDim.x) sW[t] = We1[t];
    for (int t = threadIdx.x; t < F_IN * H; t += blockDim.x) { sbe[t] = be1[t]; sroot[t] = root1[t]; }
    if (threadIdx.x < H) sb[threadIdx.x] = b1[threadIdx.x];
    __syncthreads();

    int gt = blockIdx.x * blockDim.x + threadIdx.x;
    int n = gt >> 3;
    int o = gt & 7;
    if (n >= N) return;

    float xv[F_IN];
    const float4* xp = (const float4*)(x + (size_t)n * F_IN);
    float4 v0 = xp[0], v1 = xp[1], v2 = xp[2], v3 = xp[3];
    xv[0]=v0.x; xv[1]=v0.y; xv[2]=v0.z; xv[3]=v0.w;
    xv[4]=v1.x; xv[5]=v1.y; xv[6]=v1.z; xv[7]=v1.w;
    xv[8]=v2.x; xv[9]=v2.y; xv[10]=v2.z; xv[11]=v2.w;
    xv[12]=v3.x; xv[13]=v3.y; xv[14]=v3.z; xv[15]=v3.w;

    float yv[F_EDGE];
    #pragma unroll
    for (int j = 0; j < F_EDGE; j++) {
        float acc = 0.f;
        #pragma unroll
        for (int i = 0; i < F_IN; i++) acc += xv[i] * sW[j * (F_IN * H) + i * H + o];
        yv[j] = acc;
    }
    float4* yo = (float4*)(g_y1 + (size_t)n * (F_EDGE * H) + o * F_EDGE);
    yo[0] = make_float4(yv[0], yv[1], yv[2], yv[3]);
    yo[1] = make_float4(yv[4], yv[5], yv[6], yv[7]);

    float xb = 0.f, r = sb[o];
    #pragma unroll
    for (int i = 0; i < F_IN; i++) {
        xb += xv[i] * sbe[i * H + o];
        r  += xv[i] * sroot[i * H + o];
    }
    g_xb1[n * H + o] = xb;
    g_agg1[n * H + o] = r;
}

// ---------------- edge scatter: 2 threads/edge, red.v4 ----------------
__global__ void edge_scatter(const float* __restrict__ ea_g,
                             const int*   __restrict__ ei,
                             const float* __restrict__ y,
                             const float* __restrict__ xb,
                             float*       __restrict__ agg,
                             int E)
{
    int t = blockIdx.x * blockDim.x + threadIdx.x;
    int e = t >> 1;
    int g = t & 1;             // output group: channels g*4 .. g*4+3
    if (e >= E) return;

    int src = __ldg(ei + e);
    int dst = __ldg(ei + E + e);

    const float4* eap = (const float4*)(ea_g + (size_t)e * F_EDGE);
    float4 ea0 = __ldg(eap);
    float4 ea1 = __ldg(eap + 1);

    // 128B contiguous slice: y[src][g*4 + k][j], k=0..3, j=0..7
    const float4* yp = (const float4*)(y + (size_t)src * (F_EDGE * H) + g * 32);
    float4 m = __ldg((const float4*)(xb + (size_t)src * H + g * 4));

    float4 a, b;
    a = __ldg(yp + 0); b = __ldg(yp + 1);
    m.x += ea0.x*a.x + ea0.y*a.y + ea0.z*a.z + ea0.w*a.w
         + ea1.x*b.x + ea1.y*b.y + ea1.z*b.z + ea1.w*b.w;
    a = __ldg(yp + 2); b = __ldg(yp + 3);
    m.y += ea0.x*a.x + ea0.y*a.y + ea0.z*a.z + ea0.w*a.w
         + ea1.x*b.x + ea1.y*b.y + ea1.z*b.z + ea1.w*b.w;
    a = __ldg(yp + 4); b = __ldg(yp + 5);
    m.z += ea0.x*a.x + ea0.y*a.y + ea0.z*a.z + ea0.w*a.w
         + ea1.x*b.x + ea1.y*b.y + ea1.z*b.z + ea1.w*b.w;
    a = __ldg(yp + 6); b = __ldg(yp + 7);
    m.w += ea0.x*a.x + ea0.y*a.y + ea0.z*a.z + ea0.w*a.w
         + ea1.x*b.x + ea1.y*b.y + ea1.z*b.z + ea1.w*b.w;

    red_add_v4(agg + (size_t)dst * H + g * 4, m);
}

// ---------------- kernel C: relu(layer1) + per-node precompute layer 2 ----------------
__global__ void node_mid(const float* __restrict__ We2,
                         const float* __restrict__ be2,
                         const float* __restrict__ root2,
                         const float* __restrict__ b2,
                         int N)
{
    __shared__ float sW[F_EDGE * H * H];   // 512
    __shared__ float sbe[H * H];
    __shared__ float sroot[H * H];
    __shared__ float sb[H];

    for (int t = threadIdx.x; t < F_EDGE * H * H; t += blockDim.x) sW[t] = We2[t];
    for (int t = threadIdx.x; t < H * H; t += blockDim.x) { sbe[t] = be2[t]; sroot[t] = root2[t]; }
    if (threadIdx.x < H) sb[threadIdx.x] = b2[threadIdx.x];
    __syncthreads();

    int gt = blockIdx.x * blockDim.x + threadIdx.x;
    int n = gt >> 3;
    int o = gt & 7;
    if (n >= N) return;

    float h[H];
    const float4* ap = (const float4*)(g_agg1 + (size_t)n * H);
    float4 a0 = ap[0], a1 = ap[1];
    h[0]=fmaxf(a0.x,0.f); h[1]=fmaxf(a0.y,0.f); h[2]=fmaxf(a0.z,0.f); h[3]=fmaxf(a0.w,0.f);
    h[4]=fmaxf(a1.x,0.f); h[5]=fmaxf(a1.y,0.f); h[6]=fmaxf(a1.z,0.f); h[7]=fmaxf(a1.w,0.f);

    float yv[F_EDGE];
    #pragma unroll
    for (int j = 0; j < F_EDGE; j++) {
        float acc = 0.f;
        #pragma unroll
        for (int i = 0; i < H; i++) acc += h[i] * sW[j * (H * H) + i * H + o];
        yv[j] = acc;
    }
    float4* yo = (float4*)(g_y2 + (size_t)n * (F_EDGE * H) + o * F_EDGE);
    yo[0] = make_float4(yv[0], yv[1], yv[2], yv[3]);
    yo[1] = make_float4(yv[4], yv[5], yv[6], yv[7]);

    float xb = 0.f, r = sb[o];
    #pragma unroll
    for (int i = 0; i < H; i++) {
        xb += h[i] * sbe[i * H + o];
        r  += h[i] * sroot[i * H + o];
    }
    g_xb2[n * H + o] = xb;
    g_agg2[n * H + o] = r;
}

// ---------------- kernel E0: init output with bias ----------------
__global__ void out_init(float* __restrict__ out, const float* __restrict__ blast, int G)
{
    int g = blockIdx.x * blockDim.x + threadIdx.x;
    if (g < G) out[g] = blast[0];
}

// ---------------- kernel E: relu(layer2) + pool + readout ----------------
// batch is sorted: warp-segmented reduction, one atomic per (warp, graph-run)
__global__ void pool_out(const int* __restrict__ batch,
                         const float* __restrict__ Wlast,
                         float* __restrict__ out,
                         int N)
{
    int n = blockIdx.x * blockDim.x + threadIdx.x;
    int lane = threadIdx.x & 31;
    float s = 0.f;
    int b = -1;
    if (n < N) {
        const float4* ap = (const float4*)(g_agg2 + (size_t)n * H);
        float4 a0 = ap[0], a1 = ap[1];
        s += fmaxf(a0.x,0.f) * __ldg(Wlast + 0);
        s += fmaxf(a0.y,0.f) * __ldg(Wlast + 1);
        s += fmaxf(a0.z,0.f) * __ldg(Wlast + 2);
        s += fmaxf(a0.w,0.f) * __ldg(Wlast + 3);
        s += fmaxf(a1.x,0.f) * __ldg(Wlast + 4);
        s += fmaxf(a1.y,0.f) * __ldg(Wlast + 5);
        s += fmaxf(a1.z,0.f) * __ldg(Wlast + 6);
        s += fmaxf(a1.w,0.f) * __ldg(Wlast + 7);
        b = __ldg(batch + n);
    }
    // segmented reduce over sorted keys within warp
    #pragma unroll
    for (int off = 1; off < 32; off <<= 1) {
        float s2 = __shfl_down_sync(0xffffffffu, s, off);
        int   b2 = __shfl_down_sync(0xffffffffu, b, off);
        if (lane + off < 32 && b2 == b) s += s2;
    }
    int bprev = __shfl_up_sync(0xffffffffu, b, 1);
    bool leader = (lane == 0) || (bprev != b);
    if (n < N && leader) atomicAdd(&out[b], s);
}

// ---------------- launch ----------------
extern "C" void kernel_launch(void* const* d_in, const int* in_sizes, int n_in,
                              void* d_out, int out_size)
{
    const float* x         = (const float*)d_in[0];
    const int*   edge_index= (const int*)  d_in[1];
    const float* edge_attr = (const float*)d_in[2];
    const int*   batch     = (const int*)  d_in[3];
    const float* We1       = (const float*)d_in[4];
    const float* be1       = (const float*)d_in[5];
    const float* root1     = (const float*)d_in[6];
    const float* b1        = (const float*)d_in[7];
    const float* We2       = (const float*)d_in[8];
    const float* be2       = (const float*)d_in[9];
    const float* root2     = (const float*)d_in[10];
    const float* b2        = (const float*)d_in[11];
    const float* Wlast     = (const float*)d_in[12];
    const float* blast     = (const float*)d_in[13];
    float* out = (float*)d_out;

    int N = in_sizes[0] / F_IN;
    int E = in_sizes[1] / 2;
    int G = out_size;

    float *y1, *xb1, *agg1, *y2, *xb2, *agg2;
    cudaGetSymbolAddress((void**)&y1,  g_y1);
    cudaGetSymbolAddress((void**)&xb1, g_xb1);
    cudaGetSymbolAddress((void**)&agg1,g_agg1);
    cudaGetSymbolAddress((void**)&y2,  g_y2);
    cudaGetSymbolAddress((void**)&xb2, g_xb2);
    cudaGetSymbolAddress((void**)&agg2,g_agg2);

    dim3 blk(256);
    int node_blocks = (N * H + 255) / 256;
    int edge_blocks = (E * 2 + 255) / 256;

    node_pre1<<<node_blocks, blk>>>(x, We1, be1, root1, b1, N);
    edge_scatter<<<edge_blocks, blk>>>(edge_attr, edge_index, y1, xb1, agg1, E);
    node_mid<<<node_blocks, blk>>>(We2, be2, root2, b2, N);
    edge_scatter<<<edge_blocks, blk>>>(edge_attr, edge_index, y2, xb2, agg2, E);
    out_init<<<(G + 255) / 256, blk>>>(out, blast, G);
    pool_out<<<(N + 255) / 256, blk>>>(batch, Wlast, out, N);
}

// round 6
// speedup vs baseline: 1.5291x; 1.5291x over previous
#include <cuda_runtime.h>

#define N_NODES   50000
#define N_EDGES   800000
#define F_IN      16
#define F_EDGE    8
#define H         8
#define NUM_GRAPHS 512

// ---------------- scratch (no allocations allowed) ----------------
__device__ float g_y1 [N_NODES * F_EDGE * H];   // y1[n][o][j]
__device__ float g_xb1[N_NODES * H];
__device__ float g_agg1[N_NODES * H];
__device__ float g_y2 [N_NODES * F_EDGE * H];
__device__ float g_xb2[N_NODES * H];
__device__ float g_agg2[N_NODES * H];

__device__ __forceinline__ void red_add_v4(float* p, float a, float b, float c, float d) {
    asm volatile("red.global.add.v4.f32 [%0], {%1,%2,%3,%4};"
                 :: "l"(p), "f"(a), "f"(b), "f"(c), "f"(d) : "memory");
}

// ---------------- kernel A: per-node precompute for layer 1 ----------------
// thread = (node n, out-channel o)
__global__ void node_pre1(const float* __restrict__ x,
                          const float* __restrict__ We1,
                          const float* __restrict__ be1,
                          const float* __restrict__ root1,
                          const float* __restrict__ b1,
                          int N)
{
    __shared__ float sW[F_EDGE * F_IN * H];   // 1024
    __shared__ float sbe[F_IN * H];
    __shared__ float sroot[F_IN * H];
    __shared__ float sb[H];

    for (int t = threadIdx.x; t < F_EDGE * F_IN * H; t += blockDim.x) sW[t] = We1[t];
    for (int t = threadIdx.x; t < F_IN * H; t += blockDim.x) { sbe[t] = be1[t]; sroot[t] = root1[t]; }
    if (threadIdx.x < H) sb[threadIdx.x] = b1[threadIdx.x];
    __syncthreads();

    int gt = blockIdx.x * blockDim.x + threadIdx.x;
    int n = gt >> 3;
    int o = gt & 7;
    if (n >= N) return;

    float xv[F_IN];
    const float4* xp = (const float4*)(x + (size_t)n * F_IN);
    float4 v0 = xp[0], v1 = xp[1], v2 = xp[2], v3 = xp[3];
    xv[0]=v0.x; xv[1]=v0.y; xv[2]=v0.z; xv[3]=v0.w;
    xv[4]=v1.x; xv[5]=v1.y; xv[6]=v1.z; xv[7]=v1.w;
    xv[8]=v2.x; xv[9]=v2.y; xv[10]=v2.z; xv[11]=v2.w;
    xv[12]=v3.x; xv[13]=v3.y; xv[14]=v3.z; xv[15]=v3.w;

    float yv[F_EDGE];
    #pragma unroll
    for (int j = 0; j < F_EDGE; j++) {
        float acc = 0.f;
        #pragma unroll
        for (int i = 0; i < F_IN; i++) acc += xv[i] * sW[j * (F_IN * H) + i * H + o];
        yv[j] = acc;
    }
    float4* yo = (float4*)(g_y1 + (size_t)n * (F_EDGE * H) + o * F_EDGE);
    yo[0] = make_float4(yv[0], yv[1], yv[2], yv[3]);
    yo[1] = make_float4(yv[4], yv[5], yv[6], yv[7]);

    float xb = 0.f, r = sb[o];
    #pragma unroll
    for (int i = 0; i < F_IN; i++) {
        xb += xv[i] * sbe[i * H + o];
        r  += xv[i] * sroot[i * H + o];
    }
    g_xb1[n * H + o] = xb;
    g_agg1[n * H + o] = r;
}

// ---------------- edge scatter: 8 thr/edge gather (R2 layout) + v4 RED ----------------
__global__ void edge_scatter(const float* __restrict__ ea_g,
                             const int*   __restrict__ ei,
                             const float* __restrict__ y,
                             const float* __restrict__ xb,
                             float*       __restrict__ agg,
                             int E)
{
    __shared__ float sea[32 * F_EDGE];   // 32 edges' attrs, coalesced stage
    int eb = blockIdx.x * 32;
    int t = threadIdx.x;
    int lin = eb * F_EDGE + t;
    if (lin < E * F_EDGE) sea[t] = ea_g[lin];
    __syncthreads();

    int le = t >> 3;
    int o  = t & 7;
    int e  = eb + le;
    bool valid = (e < E);

    float m = 0.f;
    int dst = 0;
    if (valid) {
        int src = __ldg(ei + e);
        dst     = __ldg(ei + E + e);

        const float* yp = y + (size_t)src * (F_EDGE * H) + o * F_EDGE;
        float4 ya = *(const float4*)yp;
        float4 yb = *(const float4*)(yp + 4);
        const float* eap = sea + le * F_EDGE;

        m = __ldg(xb + (size_t)src * H + o);
        m += eap[0]*ya.x + eap[1]*ya.y + eap[2]*ya.z + eap[3]*ya.w
           + eap[4]*yb.x + eap[5]*yb.y + eap[6]*yb.z + eap[7]*yb.w;
    }

    // assemble 4 contiguous channels into one lane, single vector RED
    unsigned mask = 0xffffffffu;
    int lane = t & 31;
    int base = lane & ~3;
    float v0 = __shfl_sync(mask, m, base);
    float v1 = __shfl_sync(mask, m, base + 1);
    float v2 = __shfl_sync(mask, m, base + 2);
    float v3 = __shfl_sync(mask, m, base + 3);

    if (valid && (lane & 3) == 0) {
        // channels (lane&4)..(lane&4)+3 of this edge
        red_add_v4(agg + (size_t)dst * H + (lane & 4), v0, v1, v2, v3);
    }
}

// ---------------- kernel C: relu(layer1) + precompute layer 2 (+ out init) ----------------
__global__ void node_mid(const float* __restrict__ We2,
                         const float* __restrict__ be2,
                         const float* __restrict__ root2,
                         const float* __restrict__ b2,
                         const float* __restrict__ blast,
                         float* __restrict__ out,
                         int N, int G)
{
    __shared__ float sW[F_EDGE * H * H];   // 512
    __shared__ float sbe[H * H];
    __shared__ float sroot[H * H];
    __shared__ float sb[H];

    for (int t = threadIdx.x; t < F_EDGE * H * H; t += blockDim.x) sW[t] = We2[t];
    for (int t = threadIdx.x; t < H * H; t += blockDim.x) { sbe[t] = be2[t]; sroot[t] = root2[t]; }
    if (threadIdx.x < H) sb[threadIdx.x] = b2[threadIdx.x];
    __syncthreads();

    int gt = blockIdx.x * blockDim.x + threadIdx.x;
    if (gt < G) out[gt] = blast[0];        // fold output-bias init into this pass

    int n = gt >> 3;
    int o = gt & 7;
    if (n >= N) return;

    float h[H];
    const float4* ap = (const float4*)(g_agg1 + (size_t)n * H);
    float4 a0 = ap[0], a1 = ap[1];
    h[0]=fmaxf(a0.x,0.f); h[1]=fmaxf(a0.y,0.f); h[2]=fmaxf(a0.z,0.f); h[3]=fmaxf(a0.w,0.f);
    h[4]=fmaxf(a1.x,0.f); h[5]=fmaxf(a1.y,0.f); h[6]=fmaxf(a1.z,0.f); h[7]=fmaxf(a1.w,0.f);

    float yv[F_EDGE];
    #pragma unroll
    for (int j = 0; j < F_EDGE; j++) {
        float acc = 0.f;
        #pragma unroll
        for (int i = 0; i < H; i++) acc += h[i] * sW[j * (H * H) + i * H + o];
        yv[j] = acc;
    }
    float4* yo = (float4*)(g_y2 + (size_t)n * (F_EDGE * H) + o * F_EDGE);
    yo[0] = make_float4(yv[0], yv[1], yv[2], yv[3]);
    yo[1] = make_float4(yv[4], yv[5], yv[6], yv[7]);

    float xb = 0.f, r = sb[o];
    #pragma unroll
    for (int i = 0; i < H; i++) {
        xb += h[i] * sbe[i * H + o];
        r  += h[i] * sroot[i * H + o];
    }
    g_xb2[n * H + o] = xb;
    g_agg2[n * H + o] = r;
}

// ---------------- kernel E: relu(layer2) + pool + readout ----------------
// batch is sorted: warp-segmented reduction, one atomic per (warp, graph-run)
__global__ void pool_out(const int* __restrict__ batch,
                         const float* __restrict__ Wlast,
                         float* __restrict__ out,
                         int N)
{
    int n = blockIdx.x * blockDim.x + threadIdx.x;
    int lane = threadIdx.x & 31;
    float s = 0.f;
    int b = -1;
    if (n < N) {
        const float4* ap = (const float4*)(g_agg2 + (size_t)n * H);
        float4 a0 = ap[0], a1 = ap[1];
        s += fmaxf(a0.x,0.f) * __ldg(Wlast + 0);
        s += fmaxf(a0.y,0.f) * __ldg(Wlast + 1);
        s += fmaxf(a0.z,0.f) * __ldg(Wlast + 2);
        s += fmaxf(a0.w,0.f) * __ldg(Wlast + 3);
        s += fmaxf(a1.x,0.f) * __ldg(Wlast + 4);
        s += fmaxf(a1.y,0.f) * __ldg(Wlast + 5);
        s += fmaxf(a1.z,0.f) * __ldg(Wlast + 6);
        s += fmaxf(a1.w,0.f) * __ldg(Wlast + 7);
        b = __ldg(batch + n);
    }
    #pragma unroll
    for (int off = 1; off < 32; off <<= 1) {
        float s2 = __shfl_down_sync(0xffffffffu, s, off);
        int   b2 = __shfl_down_sync(0xffffffffu, b, off);
        if (lane + off < 32 && b2 == b) s += s2;
    }
    int bprev = __shfl_up_sync(0xffffffffu, b, 1);
    bool leader = (lane == 0) || (bprev != b);
    if (n < N && leader) atomicAdd(&out[b], s);
}

// ---------------- launch ----------------
extern "C" void kernel_launch(void* const* d_in, const int* in_sizes, int n_in,
                              void* d_out, int out_size)
{
    const float* x         = (const float*)d_in[0];
    const int*   edge_index= (const int*)  d_in[1];
    const float* edge_attr = (const float*)d_in[2];
    const int*   batch     = (const int*)  d_in[3];
    const float* We1       = (const float*)d_in[4];
    const float* be1       = (const float*)d_in[5];
    const float* root1     = (const float*)d_in[6];
    const float* b1        = (const float*)d_in[7];
    const float* We2       = (const float*)d_in[8];
    const float* be2       = (const float*)d_in[9];
    const float* root2     = (const float*)d_in[10];
    const float* b2        = (const float*)d_in[11];
    const float* Wlast     = (const float*)d_in[12];
    const float* blast     = (const float*)d_in[13];
    float* out = (float*)d_out;

    int N = in_sizes[0] / F_IN;
    int E = in_sizes[1] / 2;
    int G = out_size;

    float *y1, *xb1, *agg1, *y2, *xb2, *agg2;
    cudaGetSymbolAddress((void**)&y1,  g_y1);
    cudaGetSymbolAddress((void**)&xb1, g_xb1);
    cudaGetSymbolAddress((void**)&agg1,g_agg1);
    cudaGetSymbolAddress((void**)&y2,  g_y2);
    cudaGetSymbolAddress((void**)&xb2, g_xb2);
    cudaGetSymbolAddress((void**)&agg2,g_agg2);

    dim3 blk(256);
    int node_blocks = (N * H + 255) / 256;
    int edge_blocks = (E + 31) / 32;

    node_pre1<<<node_blocks, blk>>>(x, We1, be1, root1, b1, N);
    edge_scatter<<<edge_blocks, blk>>>(edge_attr, edge_index, y1, xb1, agg1, E);
    node_mid<<<node_blocks, blk>>>(We2, be2, root2, b2, blast, out, N, G);
    edge_scatter<<<edge_blocks, blk>>>(edge_attr, edge_index, y2, xb2, agg2, E);
    pool_out<<<(N + 255) / 256, blk>>>(batch, Wlast, out, N);
}

// round 9
// speedup vs baseline: 1.8312x; 1.1975x over previous
#include <cuda_runtime.h>
#include <cuda_fp16.h>

#define N_NODES   50000
#define N_EDGES   800000
#define F_IN      16
#define F_EDGE    8
#define H         8
#define NUM_GRAPHS 512

// ---------------- scratch (no allocations allowed) ----------------
// y tables in fp16: one node row = 64 halves = 128B = 1 cache line
__device__ __half g_y1 [N_NODES * F_EDGE * H];
__device__ __half g_xb1[N_NODES * H];
__device__ float  g_agg1[N_NODES * H];
__device__ __half g_y2 [N_NODES * F_EDGE * H];
__device__ __half g_xb2[N_NODES * H];
__device__ float  g_agg2[N_NODES * H];

__device__ __forceinline__ void red_add_v4(float* p, float a, float b, float c, float d) {
    asm volatile("red.global.add.v4.f32 [%0], {%1,%2,%3,%4};"
                 :: "l"(p), "f"(a), "f"(b), "f"(c), "f"(d) : "memory");
}

__device__ __forceinline__ void store_row_half(__half* base, int n, int o, const float* yv) {
    __half2 p0 = __floats2half2_rn(yv[0], yv[1]);
    __half2 p1 = __floats2half2_rn(yv[2], yv[3]);
    __half2 p2 = __floats2half2_rn(yv[4], yv[5]);
    __half2 p3 = __floats2half2_rn(yv[6], yv[7]);
    uint4 u;
    u.x = *(unsigned*)&p0; u.y = *(unsigned*)&p1;
    u.z = *(unsigned*)&p2; u.w = *(unsigned*)&p3;
    *((uint4*)(base + (size_t)n * (F_EDGE * H)) + o) = u;
}

// ---------------- kernel A: per-node precompute for layer 1 ----------------
__global__ void node_pre1(const float* __restrict__ x,
                          const float* __restrict__ We1,
                          const float* __restrict__ be1,
                          const float* __restrict__ root1,
                          const float* __restrict__ b1,
                          int N)
{
    __shared__ float sW[F_EDGE * F_IN * H];   // 1024
    __shared__ float sbe[F_IN * H];
    __shared__ float sroot[F_IN * H];
    __shared__ float sb[H];

    for (int t = threadIdx.x; t < F_EDGE * F_IN * H; t += blockDim.x) sW[t] = We1[t];
    for (int t = threadIdx.x; t < F_IN * H; t += blockDim.x) { sbe[t] = be1[t]; sroot[t] = root1[t]; }
    if (threadIdx.x < H) sb[threadIdx.x] = b1[threadIdx.x];
    __syncthreads();

    int gt = blockIdx.x * blockDim.x + threadIdx.x;
    int n = gt >> 3;
    int o = gt & 7;
    if (n >= N) return;

    float xv[F_IN];
    const float4* xp = (const float4*)(x + (size_t)n * F_IN);
    float4 v0 = xp[0], v1 = xp[1], v2 = xp[2], v3 = xp[3];
    xv[0]=v0.x; xv[1]=v0.y; xv[2]=v0.z; xv[3]=v0.w;
    xv[4]=v1.x; xv[5]=v1.y; xv[6]=v1.z; xv[7]=v1.w;
    xv[8]=v2.x; xv[9]=v2.y; xv[10]=v2.z; xv[11]=v2.w;
    xv[12]=v3.x; xv[13]=v3.y; xv[14]=v3.z; xv[15]=v3.w;

    float yv[F_EDGE];
    #pragma unroll
    for (int j = 0; j < F_EDGE; j++) {
        float acc = 0.f;
        #pragma unroll
        for (int i = 0; i < F_IN; i++) acc += xv[i] * sW[j * (F_IN * H) + i * H + o];
        yv[j] = acc;
    }
    store_row_half(g_y1, n, o, yv);

    float xb = 0.f, r = sb[o];
    #pragma unroll
    for (int i = 0; i < F_IN; i++) {
        xb += xv[i] * sbe[i * H + o];
        r  += xv[i] * sroot[i * H + o];
    }
    g_xb1[n * H + o] = __float2half_rn(xb);
    g_agg1[n * H + o] = r;
}

// ---------------- edge scatter: 8 thr/edge, fp16 gather (1 line/edge), v4 RED ----------------
__global__ void edge_scatter(const float* __restrict__ ea_g,
                             const int*   __restrict__ ei,
                             const __half* __restrict__ y,
                             const __half* __restrict__ xb,
                             float*       __restrict__ agg,
                             int E)
{
    __shared__ float sea[32 * F_EDGE];   // 32 edges' attrs, coalesced stage
    int eb = blockIdx.x * 32;
    int t = threadIdx.x;
    int lin = eb * F_EDGE + t;
    if (lin < E * F_EDGE) sea[t] = ea_g[lin];
    __syncthreads();

    int le = t >> 3;
    int o  = t & 7;
    int e  = eb + le;
    bool valid = (e < E);

    float m = 0.f;
    int dst = 0;
    if (valid) {
        int src = __ldg(ei + e);
        dst     = __ldg(ei + E + e);

        // one 16B load per lane; 8 lanes cover the node's whole 128B row
        uint4 yv = __ldg((const uint4*)(y + (size_t)src * (F_EDGE * H)) + o);
        float2 f0 = __half22float2(*(__half2*)&yv.x);
        float2 f1 = __half22float2(*(__half2*)&yv.y);
        float2 f2 = __half22float2(*(__half2*)&yv.z);
        float2 f3 = __half22float2(*(__half2*)&yv.w);
        const float* eap = sea + le * F_EDGE;

        m = __half2float(__ldg(xb + (size_t)src * H + o));
        m += eap[0]*f0.x + eap[1]*f0.y + eap[2]*f1.x + eap[3]*f1.y
           + eap[4]*f2.x + eap[5]*f2.y + eap[6]*f3.x + eap[7]*f3.y;
    }

    // assemble 4 contiguous channels into one lane, single vector RED
    unsigned mask = 0xffffffffu;
    int lane = t & 31;
    int base = lane & ~3;
    float v0 = __shfl_sync(mask, m, base);
    float v1 = __shfl_sync(mask, m, base + 1);
    float v2 = __shfl_sync(mask, m, base + 2);
    float v3 = __shfl_sync(mask, m, base + 3);

    if (valid && (lane & 3) == 0) {
        red_add_v4(agg + (size_t)dst * H + (lane & 4), v0, v1, v2, v3);
    }
}

// ---------------- kernel C: relu(layer1) + precompute layer 2 (+ out init) ----------------
__global__ void node_mid(const float* __restrict__ We2,
                         const float* __restrict__ be2,
                         const float* __restrict__ root2,
                         const float* __restrict__ b2,
                         const float* __restrict__ blast,
                         float* __restrict__ out,
                         int N, int G)
{
    __shared__ float sW[F_EDGE * H * H];   // 512
    __shared__ float sbe[H * H];
    __shared__ float sroot[H * H];
    __shared__ float sb[H];

    for (int t = threadIdx.x; t < F_EDGE * H * H; t += blockDim.x) sW[t] = We2[t];
    for (int t = threadIdx.x; t < H * H; t += blockDim.x) { sbe[t] = be2[t]; sroot[t] = root2[t]; }
    if (threadIdx.x < H) sb[threadIdx.x] = b2[threadIdx.x];
    __syncthreads();

    int gt = blockIdx.x * blockDim.x + threadIdx.x;
    if (gt < G) out[gt] = blast[0];        // fold output-bias init into this pass

    int n = gt >> 3;
    int o = gt & 7;
    if (n >= N) return;

    float h[H];
    const float4* ap = (const float4*)(g_agg1 + (size_t)n * H);
    float4 a0 = ap[0], a1 = ap[1];
    h[0]=fmaxf(a0.x,0.f); h[1]=fmaxf(a0.y,0.f); h[2]=fmaxf(a0.z,0.f); h[3]=fmaxf(a0.w,0.f);
    h[4]=fmaxf(a1.x,0.f); h[5]=fmaxf(a1.y,0.f); h[6]=fmaxf(a1.z,0.f); h[7]=fmaxf(a1.w,0.f);

    float yv[F_EDGE];
    #pragma unroll
    for (int j = 0; j < F_EDGE; j++) {
        float acc = 0.f;
        #pragma unroll
        for (int i = 0; i < H; i++) acc += h[i] * sW[j * (H * H) + i * H + o];
        yv[j] = acc;
    }
    store_row_half(g_y2, n, o, yv);

    float xb = 0.f, r = sb[o];
    #pragma unroll
    for (int i = 0; i < H; i++) {
        xb += h[i] * sbe[i * H + o];
        r  += h[i] * sroot[i * H + o];
    }
    g_xb2[n * H + o] = __float2half_rn(xb);
    g_agg2[n * H + o] = r;
}

// ---------------- kernel E: relu(layer2) + pool + readout ----------------
__global__ void pool_out(const int* __restrict__ batch,
                         const float* __restrict__ Wlast,
                         float* __restrict__ out,
                         int N)
{
    int n = blockIdx.x * blockDim.x + threadIdx.x;
    int lane = threadIdx.x & 31;
    float s = 0.f;
    int b = -1;
    if (n < N) {
        const float4* ap = (const float4*)(g_agg2 + (size_t)n * H);
        float4 a0 = ap[0], a1 = ap[1];
        s += fmaxf(a0.x,0.f) * __ldg(Wlast + 0);
        s += fmaxf(a0.y,0.f) * __ldg(Wlast + 1);
        s += fmaxf(a0.z,0.f) * __ldg(Wlast + 2);
        s += fmaxf(a0.w,0.f) * __ldg(Wlast + 3);
        s += fmaxf(a1.x,0.f) * __ldg(Wlast + 4);
        s += fmaxf(a1.y,0.f) * __ldg(Wlast + 5);
        s += fmaxf(a1.z,0.f) * __ldg(Wlast + 6);
        s += fmaxf(a1.w,0.f) * __ldg(Wlast + 7);
        b = __ldg(batch + n);
    }
    #pragma unroll
    for (int off = 1; off < 32; off <<= 1) {
        float s2 = __shfl_down_sync(0xffffffffu, s, off);
        int   b2 = __shfl_down_sync(0xffffffffu, b, off);
        if (lane + off < 32 && b2 == b) s += s2;
    }
    int bprev = __shfl_up_sync(0xffffffffu, b, 1);
    bool leader = (lane == 0) || (bprev != b);
    if (n < N && leader) atomicAdd(&out[b], s);
}

// ---------------- launch ----------------
extern "C" void kernel_launch(void* const* d_in, const int* in_sizes, int n_in,
                              void* d_out, int out_size)
{
    const float* x         = (const float*)d_in[0];
    const int*   edge_index= (const int*)  d_in[1];
    const float* edge_attr = (const float*)d_in[2];
    const int*   batch     = (const int*)  d_in[3];
    const float* We1       = (const float*)d_in[4];
    const float* be1       = (const float*)d_in[5];
    const float* root1     = (const float*)d_in[6];
    const float* b1        = (const float*)d_in[7];
    const float* We2       = (const float*)d_in[8];
    const float* be2       = (const float*)d_in[9];
    const float* root2     = (const float*)d_in[10];
    const float* b2        = (const float*)d_in[11];
    const float* Wlast     = (const float*)d_in[12];
    const float* blast     = (const float*)d_in[13];
    float* out = (float*)d_out;

    int N = in_sizes[0] / F_IN;
    int E = in_sizes[1] / 2;
    int G = out_size;

    __half *y1, *xb1, *y2, *xb2;
    float *agg1, *agg2;
    cudaGetSymbolAddress((void**)&y1,  g_y1);
    cudaGetSymbolAddress((void**)&xb1, g_xb1);
    cudaGetSymbolAddress((void**)&agg1,g_agg1);
    cudaGetSymbolAddress((void**)&y2,  g_y2);
    cudaGetSymbolAddress((void**)&xb2, g_xb2);
    cudaGetSymbolAddress((void**)&agg2,g_agg2);

    dim3 blk(256);
    int node_blocks = (N * H + 255) / 256;
    int edge_blocks = (E + 31) / 32;

    node_pre1<<<node_blocks, blk>>>(x, We1, be1, root1, b1, N);
    edge_scatter<<<edge_blocks, blk>>>(edge_attr, edge_index, y1, xb1, agg1, E);
    node_mid<<<node_blocks, blk>>>(We2, be2, root2, b2, blast, out, N, G);
    edge_scatter<<<edge_blocks, blk>>>(edge_attr, edge_index, y2, xb2, agg2, E);
    pool_out<<<(N + 255) / 256, blk>>>(batch, Wlast, out, N);
}

// round 11
// speedup vs baseline: 2.0648x; 1.1276x over previous
#include <cuda_runtime.h>
#include <cuda_fp16.h>

#define N_NODES   50000
#define N_EDGES   800000
#define F_IN      16
#define F_EDGE    8
#define H         8
#define NUM_GRAPHS 512

// ---------------- scratch (no allocations allowed) ----------------
// y tables in fp16: one node row = 64 halves = 128B = 1 cache line
__device__ __half g_y1 [N_NODES * F_EDGE * H];
__device__ __half g_xb1[N_NODES * H];
__device__ float  g_agg1[N_NODES * H];
__device__ __half g_y2 [N_NODES * F_EDGE * H];
__device__ __half g_xb2[N_NODES * H];
__device__ float  g_agg2[N_NODES * H];

__device__ __forceinline__ void red_add_v4(float* p, float a, float b, float c, float d) {
    asm volatile("red.global.add.v4.f32 [%0], {%1,%2,%3,%4};"
                 :: "l"(p), "f"(a), "f"(b), "f"(c), "f"(d) : "memory");
}

__device__ __forceinline__ void store_row_half(__half* base, int n, int o, const float* yv) {
    __half2 p0 = __floats2half2_rn(yv[0], yv[1]);
    __half2 p1 = __floats2half2_rn(yv[2], yv[3]);
    __half2 p2 = __floats2half2_rn(yv[4], yv[5]);
    __half2 p3 = __floats2half2_rn(yv[6], yv[7]);
    uint4 u;
    u.x = *(unsigned*)&p0; u.y = *(unsigned*)&p1;
    u.z = *(unsigned*)&p2; u.w = *(unsigned*)&p3;
    *((uint4*)(base + (size_t)n * (F_EDGE * H)) + o) = u;
}

// ---------------- kernel A: per-node precompute for layer 1 ----------------
__global__ void node_pre1(const float* __restrict__ x,
                          const float* __restrict__ We1,
                          const float* __restrict__ be1,
                          const float* __restrict__ root1,
                          const float* __restrict__ b1,
                          int N)
{
    __shared__ float sW[F_EDGE * F_IN * H];   // 1024
    __shared__ float sbe[F_IN * H];
    __shared__ float sroot[F_IN * H];
    __shared__ float sb[H];

    for (int t = threadIdx.x; t < F_EDGE * F_IN * H; t += blockDim.x) sW[t] = We1[t];
    for (int t = threadIdx.x; t < F_IN * H; t += blockDim.x) { sbe[t] = be1[t]; sroot[t] = root1[t]; }
    if (threadIdx.x < H) sb[threadIdx.x] = b1[threadIdx.x];
    __syncthreads();

    int gt = blockIdx.x * blockDim.x + threadIdx.x;
    int n = gt >> 3;
    int o = gt & 7;
    if (n >= N) return;

    float xv[F_IN];
    const float4* xp = (const float4*)(x + (size_t)n * F_IN);
    float4 v0 = xp[0], v1 = xp[1], v2 = xp[2], v3 = xp[3];
    xv[0]=v0.x; xv[1]=v0.y; xv[2]=v0.z; xv[3]=v0.w;
    xv[4]=v1.x; xv[5]=v1.y; xv[6]=v1.z; xv[7]=v1.w;
    xv[8]=v2.x; xv[9]=v2.y; xv[10]=v2.z; xv[11]=v2.w;
    xv[12]=v3.x; xv[13]=v3.y; xv[14]=v3.z; xv[15]=v3.w;

    float yv[F_EDGE];
    #pragma unroll
    for (int j = 0; j < F_EDGE; j++) {
        float acc = 0.f;
        #pragma unroll
        for (int i = 0; i < F_IN; i++) acc += xv[i] * sW[j * (F_IN * H) + i * H + o];
        yv[j] = acc;
    }
    store_row_half(g_y1, n, o, yv);

    float xb = 0.f, r = sb[o];
    #pragma unroll
    for (int i = 0; i < F_IN; i++) {
        xb += xv[i] * sbe[i * H + o];
        r  += xv[i] * sroot[i * H + o];
    }
    g_xb1[n * H + o] = __float2half_rn(xb);
    g_agg1[n * H + o] = r;
}

// ---------------- edge scatter: 8 thr/edge, direct coalesced attr LDG, v4 RED ----------------
// warp = 4 edges; an edge's 8 lanes each own one output channel.
// edge_attr for a warp's 4 edges = contiguous 128B-aligned 256B -> two LDG.128, 1 wf each.
__global__ void edge_scatter(const float* __restrict__ ea_g,
                             const int*   __restrict__ ei,
                             const __half* __restrict__ y,
                             const __half* __restrict__ xb,
                             float*       __restrict__ agg,
                             int E)
{
    int t = blockIdx.x * blockDim.x + threadIdx.x;
    int e = t >> 3;
    int o = t & 7;
    bool valid = (e < E);

    float m = 0.f;
    int dst = 0;
    if (valid) {
        int src = __ldg(ei + e);
        dst     = __ldg(ei + E + e);

        // direct edge-attr load: lanes of one edge read the same two 16B chunks (broadcast);
        // warp-wide the 4 edges cover one 128B line per instruction.
        const float4* eap = (const float4*)(ea_g + (size_t)e * F_EDGE);
        float4 ea0 = __ldg(eap);
        float4 ea1 = __ldg(eap + 1);

        // one 16B load per lane; 8 lanes cover the node's whole 128B fp16 row
        uint4 yv = __ldg((const uint4*)(y + (size_t)src * (F_EDGE * H)) + o);
        float2 f0 = __half22float2(*(__half2*)&yv.x);
        float2 f1 = __half22float2(*(__half2*)&yv.y);
        float2 f2 = __half22float2(*(__half2*)&yv.z);
        float2 f3 = __half22float2(*(__half2*)&yv.w);

        m = __half2float(__ldg(xb + (size_t)src * H + o));
        m += ea0.x*f0.x + ea0.y*f0.y + ea0.z*f1.x + ea0.w*f1.y
           + ea1.x*f2.x + ea1.y*f2.y + ea1.z*f3.x + ea1.w*f3.y;
    }

    // assemble 4 contiguous channels into one lane, single vector RED
    unsigned mask = 0xffffffffu;
    int lane = t & 31;
    int base = lane & ~3;
    float v0 = __shfl_sync(mask, m, base);
    float v1 = __shfl_sync(mask, m, base + 1);
    float v2 = __shfl_sync(mask, m, base + 2);
    float v3 = __shfl_sync(mask, m, base + 3);

    if (valid && (lane & 3) == 0) {
        red_add_v4(agg + (size_t)dst * H + (lane & 4), v0, v1, v2, v3);
    }
}

// ---------------- kernel C: relu(layer1) + precompute layer 2 (+ out init) ----------------
__global__ void node_mid(const float* __restrict__ We2,
                         const float* __restrict__ be2,
                         const float* __restrict__ root2,
                         const float* __restrict__ b2,
                         const float* __restrict__ blast,
                         float* __restrict__ out,
                         int N, int G)
{
    __shared__ float sW[F_EDGE * H * H];   // 512
    __shared__ float sbe[H * H];
    __shared__ float sroot[H * H];
    __shared__ float sb[H];

    for (int t = threadIdx.x; t < F_EDGE * H * H; t += blockDim.x) sW[t] = We2[t];
    for (int t = threadIdx.x; t < H * H; t += blockDim.x) { sbe[t] = be2[t]; sroot[t] = root2[t]; }
    if (threadIdx.x < H) sb[threadIdx.x] = b2[threadIdx.x];
    __syncthreads();

    int gt = blockIdx.x * blockDim.x + threadIdx.x;
    if (gt < G) out[gt] = blast[0];        // fold output-bias init into this pass

    int n = gt >> 3;
    int o = gt & 7;
    if (n >= N) return;

    float h[H];
    const float4* ap = (const float4*)(g_agg1 + (size_t)n * H);
    float4 a0 = ap[0], a1 = ap[1];
    h[0]=fmaxf(a0.x,0.f); h[1]=fmaxf(a0.y,0.f); h[2]=fmaxf(a0.z,0.f); h[3]=fmaxf(a0.w,0.f);
    h[4]=fmaxf(a1.x,0.f); h[5]=fmaxf(a1.y,0.f); h[6]=fmaxf(a1.z,0.f); h[7]=fmaxf(a1.w,0.f);

    float yv[F_EDGE];
    #pragma unroll
    for (int j = 0; j < F_EDGE; j++) {
        float acc = 0.f;
        #pragma unroll
        for (int i = 0; i < H; i++) acc += h[i] * sW[j * (H * H) + i * H + o];
        yv[j] = acc;
    }
    store_row_half(g_y2, n, o, yv);

    float xb = 0.f, r = sb[o];
    #pragma unroll
    for (int i = 0; i < H; i++) {
        xb += h[i] * sbe[i * H + o];
        r  += h[i] * sroot[i * H + o];
    }
    g_xb2[n * H + o] = __float2half_rn(xb);
    g_agg2[n * H + o] = r;
}

// ---------------- kernel E: relu(layer2) + pool + readout ----------------
__global__ void pool_out(const int* __restrict__ batch,
                         const float* __restrict__ Wlast,
                         float* __restrict__ out,
                         int N)
{
    int n = blockIdx.x * blockDim.x + threadIdx.x;
    int lane = threadIdx.x & 31;
    float s = 0.f;
    int b = -1;
    if (n < N) {
        const float4* ap = (const float4*)(g_agg2 + (size_t)n * H);
        float4 a0 = ap[0], a1 = ap[1];
        s += fmaxf(a0.x,0.f) * __ldg(Wlast + 0);
        s += fmaxf(a0.y,0.f) * __ldg(Wlast + 1);
        s += fmaxf(a0.z,0.f) * __ldg(Wlast + 2);
        s += fmaxf(a0.w,0.f) * __ldg(Wlast + 3);
        s += fmaxf(a1.x,0.f) * __ldg(Wlast + 4);
        s += fmaxf(a1.y,0.f) * __ldg(Wlast + 5);
        s += fmaxf(a1.z,0.f) * __ldg(Wlast + 6);
        s += fmaxf(a1.w,0.f) * __ldg(Wlast + 7);
        b = __ldg(batch + n);
    }
    #pragma unroll
    for (int off = 1; off < 32; off <<= 1) {
        float s2 = __shfl_down_sync(0xffffffffu, s, off);
        int   b2 = __shfl_down_sync(0xffffffffu, b, off);
        if (lane + off < 32 && b2 == b) s += s2;
    }
    int bprev = __shfl_up_sync(0xffffffffu, b, 1);
    bool leader = (lane == 0) || (bprev != b);
    if (n < N && leader) atomicAdd(&out[b], s);
}

// ---------------- launch ----------------
extern "C" void kernel_launch(void* const* d_in, const int* in_sizes, int n_in,
                              void* d_out, int out_size)
{
    const float* x         = (const float*)d_in[0];
    const int*   edge_index= (const int*)  d_in[1];
    const float* edge_attr = (const float*)d_in[2];
    const int*   batch     = (const int*)  d_in[3];
    const float* We1       = (const float*)d_in[4];
    const float* be1       = (const float*)d_in[5];
    const float* root1     = (const float*)d_in[6];
    const float* b1        = (const float*)d_in[7];
    const float* We2       = (const float*)d_in[8];
    const float* be2       = (const float*)d_in[9];
    const float* root2     = (const float*)d_in[10];
    const float* b2        = (const float*)d_in[11];
    const float* Wlast     = (const float*)d_in[12];
    const float* blast     = (const float*)d_in[13];
    float* out = (float*)d_out;

    int N = in_sizes[0] / F_IN;
    int E = in_sizes[1] / 2;
    int G = out_size;

    __half *y1, *xb1, *y2, *xb2;
    float *agg1, *agg2;
    cudaGetSymbolAddress((void**)&y1,  g_y1);
    cudaGetSymbolAddress((void**)&xb1, g_xb1);
    cudaGetSymbolAddress((void**)&agg1,g_agg1);
    cudaGetSymbolAddress((void**)&y2,  g_y2);
    cudaGetSymbolAddress((void**)&xb2, g_xb2);
    cudaGetSymbolAddress((void**)&agg2,g_agg2);

    dim3 blk(256);
    int node_blocks = (N * H + 255) / 256;
    int edge_blocks = (E * H + 255) / 256;

    node_pre1<<<node_blocks, blk>>>(x, We1, be1, root1, b1, N);
    edge_scatter<<<edge_blocks, blk>>>(edge_attr, edge_index, y1, xb1, agg1, E);
    node_mid<<<node_blocks, blk>>>(We2, be2, root2, b2, blast, out, N, G);
    edge_scatter<<<edge_blocks, blk>>>(edge_attr, edge_index, y2, xb2, agg2, E);
    pool_out<<<(N + 255) / 256, blk>>>(batch, Wlast, out, N);
}